// round 14
// baseline (speedup 1.0000x reference)
#include <cuda_runtime.h>
#include <cuda_fp16.h>

#define BB 8
#define NN 5000
#define EE 100000
#define DD 128
#define NB (BB * NN)        // 40000
#define NE (BB * EE)        // 800000

typedef unsigned long long u64;
typedef unsigned int u32;

// Scratch (allocation-free: __device__ globals)
__device__ __align__(16) int   g_deg[NB];
__device__ __align__(16) int   g_off[NB];
__device__ __align__(16) int   g_cursor[NB];
__device__ __align__(16) int2  g_bin[NE];
__device__ __align__(16) uint2 g_xh[NB * DD / 4];     // x as 4xhalf chunks
__device__ __align__(16) uint2 g_meanh[NB * DD / 4];  // mean as 4xhalf chunks

// ---------------------------------------------------------------------------
// K0a: zero degree counters  (MUST precede hist — same stream as hist)
// ---------------------------------------------------------------------------
__global__ void zero_deg_kernel() {
    int i = blockIdx.x * blockDim.x + threadIdx.x;
    if (i < NB) g_deg[i] = 0;
}

// ---------------------------------------------------------------------------
// K0b: convert x -> fp16  (independent; overlaps the CSR chain)
// ---------------------------------------------------------------------------
__global__ void conv_kernel(const float* __restrict__ x) {
    int i = blockIdx.x * blockDim.x + threadIdx.x;
    if (i < NB * DD / 4) {
        float4 v = __ldg(&((const float4*)x)[i]);
        __half2 h0 = __floats2half2_rn(v.x, v.y);
        __half2 h1 = __floats2half2_rn(v.z, v.w);
        g_xh[i] = make_uint2(*(u32*)&h0, *(u32*)&h1);
    }
}

// ---------------------------------------------------------------------------
// K1: histogram of edge targets (4 edges/thread)   (round-5 proven)
// ---------------------------------------------------------------------------
__global__ void hist_kernel(const int* __restrict__ ei) {
    int t = blockIdx.x * blockDim.x + threadIdx.x;
    int base = t * 4;
    if (base >= NE) return;
    int b = base / EE;
    int e = base - b * EE;
    int4 t4 = __ldg((const int4*)&ei[(size_t)b * 2 * EE + EE + e]);
    int* deg = g_deg + b * NN;
    atomicAdd(&deg[t4.x], 1);
    atomicAdd(&deg[t4.y], 1);
    atomicAdd(&deg[t4.z], 1);
    atomicAdd(&deg[t4.w], 1);
}

// ---------------------------------------------------------------------------
// K2: exclusive prefix sum over 40000 degrees   (round-5 proven)
// ---------------------------------------------------------------------------
__global__ void __launch_bounds__(1024, 1) scan_kernel() {
    __shared__ int part[1024];
    const int t = threadIdx.x;
    const int CH = 40;
    int lo = t * CH;
    if (lo < NB) {
        const int4* d4 = (const int4*)(g_deg + lo);
        int s = 0;
#pragma unroll
        for (int i = 0; i < CH / 4; ++i) {
            int4 v = d4[i];
            s += v.x + v.y + v.z + v.w;
        }
        part[t] = s;
    } else {
        part[t] = 0;
    }
    __syncthreads();

    for (int o = 1; o < 1024; o <<= 1) {
        int v = (t >= o) ? part[t - o] : 0;
        __syncthreads();
        part[t] += v;
        __syncthreads();
    }

    if (lo < NB) {
        int run = (t > 0) ? part[t - 1] : 0;
        const int4* d4 = (const int4*)(g_deg + lo);
        int4* o4 = (int4*)(g_off + lo);
        int4* c4 = (int4*)(g_cursor + lo);
#pragma unroll
        for (int i = 0; i < CH / 4; ++i) {
            int4 v = d4[i];
            int4 w;
            w.x = run; run += v.x;
            w.y = run; run += v.y;
            w.z = run; run += v.z;
            w.w = run; run += v.w;
            o4[i] = w;
            c4[i] = w;
        }
    }
}

// ---------------------------------------------------------------------------
// K3: fill bins (4 edges/thread)   (round-5 proven)
// ---------------------------------------------------------------------------
__global__ void fill_kernel(const int* __restrict__ ei,
                            const float* __restrict__ em) {
    int t = blockIdx.x * blockDim.x + threadIdx.x;
    int base = t * 4;
    if (base >= NE) return;
    int b = base / EE;
    int e = base - b * EE;
    const int* eb = ei + (size_t)b * 2 * EE;
    int4 s4 = __ldg((const int4*)&eb[e]);
    int4 t4 = __ldg((const int4*)&eb[EE + e]);
    float4 m4 = __ldg((const float4*)&em[(size_t)b * EE + e]);
    int* cur = g_cursor + b * NN;
    int p0 = atomicAdd(&cur[t4.x], 1);
    int p1 = atomicAdd(&cur[t4.y], 1);
    int p2 = atomicAdd(&cur[t4.z], 1);
    int p3 = atomicAdd(&cur[t4.w], 1);
    g_bin[p0] = make_int2(s4.x, __float_as_int(m4.x));
    g_bin[p1] = make_int2(s4.y, __float_as_int(m4.y));
    g_bin[p2] = make_int2(s4.z, __float_as_int(m4.z));
    g_bin[p3] = make_int2(s4.w, __float_as_int(m4.w));
}

// ---------------------------------------------------------------------------
// K4: gather over node range [g0, g1)   (round-5 proven shape)
// ---------------------------------------------------------------------------
__global__ void gather_kernel(int g0, int g1) {
    int g = g0 + ((blockIdx.x * blockDim.x + threadIdx.x) >> 5);
    int lane = threadIdx.x & 31;
    if (g >= g1) return;
    int b = g / NN;

    const int deg = g_deg[g];
    const int off = g_off[g];
    const uint2* xr = g_xh + (size_t)b * NN * 32;
    const int2* bin = g_bin + off;

    float4 acc = make_float4(0.f, 0.f, 0.f, 0.f);
    float cm = 0.f;

#define EDGE_FMA(u, m)                                                        \
    {                                                                         \
        float2 a = __half22float2(*(__half2*)&(u).x);                         \
        float2 c = __half22float2(*(__half2*)&(u).y);                         \
        acc.x = fmaf(a.x, (m), acc.x);                                        \
        acc.y = fmaf(a.y, (m), acc.y);                                        \
        acc.z = fmaf(c.x, (m), acc.z);                                        \
        acc.w = fmaf(c.y, (m), acc.w);                                        \
        cm += (m);                                                            \
    }

    int j = 0;
    for (; j + 4 <= deg; j += 4) {
        int2 r0 = __ldg(&bin[j]);
        int2 r1 = __ldg(&bin[j + 1]);
        int2 r2 = __ldg(&bin[j + 2]);
        int2 r3 = __ldg(&bin[j + 3]);
        uint2 u0 = __ldg(&xr[(size_t)(u32)r0.x * 32 + lane]);
        uint2 u1 = __ldg(&xr[(size_t)(u32)r1.x * 32 + lane]);
        uint2 u2 = __ldg(&xr[(size_t)(u32)r2.x * 32 + lane]);
        uint2 u3 = __ldg(&xr[(size_t)(u32)r3.x * 32 + lane]);
        EDGE_FMA(u0, __int_as_float(r0.y))
        EDGE_FMA(u1, __int_as_float(r1.y))
        EDGE_FMA(u2, __int_as_float(r2.y))
        EDGE_FMA(u3, __int_as_float(r3.y))
    }
    for (; j < deg; ++j) {
        int2 r = __ldg(&bin[j]);
        uint2 u = __ldg(&xr[(size_t)(u32)r.x * 32 + lane]);
        EDGE_FMA(u, __int_as_float(r.y))
    }
#undef EDGE_FMA

    float inv = 1.f / fmaxf(cm, 1.f);
    __half2 h0 = __floats2half2_rn(acc.x * inv, acc.y * inv);
    __half2 h1 = __floats2half2_rn(acc.z * inv, acc.w * inv);
    g_meanh[(size_t)g * 32 + lane] = make_uint2(*(u32*)&h0, *(u32*)&h1);
}

// ---------------------------------------------------------------------------
// K5: fused HMMA GEMM + relu + LN + mask, over tile range [tile0, tile1).
// (round-5 proven body; persistent blocks within the range)
// ---------------------------------------------------------------------------
#define FUSED_THREADS 256
#define IN_PITCH 264
#define W_PITCH_H 136
#define SMEM_WH_BYTES (256 * W_PITCH_H * 2)
#define SMEM_IN_BYTES (128 * IN_PITCH * 2)
#define SMEM_CONST_BYTES (3 * 128 * 4)
#define FUSED_SMEM_BYTES (SMEM_WH_BYTES + SMEM_IN_BYTES + SMEM_CONST_BYTES)
#define NTILES ((NB + 127) / 128)             // 313
#define TSPLIT 157                            // pipeline split (tile units)

__device__ __forceinline__ u32 smem_u32(const void* p) {
    u32 a;
    asm("{ .reg .u64 t; cvta.to.shared.u64 t, %1; cvt.u32.u64 %0, t; }"
        : "=r"(a) : "l"(p));
    return a;
}
__device__ __forceinline__ void ldsm_x4(u32& r0, u32& r1, u32& r2, u32& r3, u32 a) {
    asm volatile("ldmatrix.sync.aligned.m8n8.x4.shared.b16 {%0,%1,%2,%3}, [%4];"
                 : "=r"(r0), "=r"(r1), "=r"(r2), "=r"(r3) : "r"(a));
}
__device__ __forceinline__ void ldsm_x4t(u32& r0, u32& r1, u32& r2, u32& r3, u32 a) {
    asm volatile("ldmatrix.sync.aligned.m8n8.x4.trans.shared.b16 {%0,%1,%2,%3}, [%4];"
                 : "=r"(r0), "=r"(r1), "=r"(r2), "=r"(r3) : "r"(a));
}
__device__ __forceinline__ void mma16816(float* c, u32 a0, u32 a1, u32 a2, u32 a3,
                                         u32 b0, u32 b1) {
    asm volatile(
        "mma.sync.aligned.m16n8k16.row.col.f32.f16.f16.f32 "
        "{%0,%1,%2,%3}, {%4,%5,%6,%7}, {%8,%9}, {%0,%1,%2,%3};"
        : "+f"(c[0]), "+f"(c[1]), "+f"(c[2]), "+f"(c[3])
        : "r"(a0), "r"(a1), "r"(a2), "r"(a3), "r"(b0), "r"(b1));
}

__global__ void __launch_bounds__(FUSED_THREADS, 1)
fused_kernel(const float* __restrict__ Wself,
             const float* __restrict__ bself,
             const float* __restrict__ Wnb,
             const float* __restrict__ bnb,
             const float* __restrict__ gamma,
             const float* __restrict__ beta,
             const float* __restrict__ nmask,
             float* __restrict__ out,
             int tile0, int tile1) {
    extern __shared__ char sm[];
    __half* Wh = (__half*)sm;
    __half* inSh = (__half*)(sm + SMEM_WH_BYTES);
    float* bias_sm = (float*)(sm + SMEM_WH_BYTES + SMEM_IN_BYTES);
    float* gm_sm = bias_sm + 128;
    float* bt_sm = gm_sm + 128;

    const int tid = threadIdx.x;
    const int lane = tid & 31;
    const int wid = tid >> 5;

    for (int i = tid; i < 256 * 128; i += FUSED_THREADS) {
        int k = i >> 7;
        int n = i & 127;
        float w = (k < 128) ? __ldg(&Wself[k * 128 + n])
                            : __ldg(&Wnb[(k - 128) * 128 + n]);
        Wh[k * W_PITCH_H + n] = __float2half_rn(w);
    }
    if (tid < 128) {
        bias_sm[tid] = __ldg(&bself[tid]) + __ldg(&bnb[tid]);
        gm_sm[tid] = __ldg(&gamma[tid]);
        bt_sm[tid] = __ldg(&beta[tid]);
    }
    __syncthreads();

    const u32 in_u = smem_u32(inSh);
    const u32 wh_u = smem_u32(Wh);
    const u32 a_row_off = (u32)(wid * 16 + (lane & 15)) * (IN_PITCH * 2)
                        + (u32)((lane >> 4) * 8) * 2;
    const u32 b_row_lane = (u32)(lane & 15) * (W_PITCH_H * 2);
    const u32 b_col_lane = (u32)((lane >> 4) * 8) * 2;

    for (int tile = tile0 + blockIdx.x; tile < tile1; tile += gridDim.x) {
        const int node0 = tile * 128;

        for (int i = tid; i < 128 * 64; i += FUSED_THREADS) {
            int nl = i >> 6;
            int c = i & 63;
            int gn = node0 + nl;
            uint2 v = make_uint2(0u, 0u);
            if (gn < NB)
                v = (c < 32) ? __ldg(&g_xh[(size_t)gn * 32 + c])
                             : __ldg(&g_meanh[(size_t)gn * 32 + (c - 32)]);
            *(uint2*)((char*)inSh + (size_t)nl * (IN_PITCH * 2) + (size_t)c * 8) = v;
        }
        __syncthreads();

        float acc[16][4];
#pragma unroll
        for (int j = 0; j < 16; ++j) {
            float2 bv = *(float2*)&bias_sm[j * 8 + (lane & 3) * 2];
            acc[j][0] = bv.x; acc[j][1] = bv.y;
            acc[j][2] = bv.x; acc[j][3] = bv.y;
        }

#pragma unroll 1
        for (int ks = 0; ks < 16; ++ks) {
            u32 a0, a1, a2, a3;
            ldsm_x4(a0, a1, a2, a3, in_u + a_row_off + (u32)ks * 32);
            u32 brow = wh_u + (u32)ks * 16 * (W_PITCH_H * 2) + b_row_lane + b_col_lane;
#pragma unroll
            for (int jt = 0; jt < 8; ++jt) {
                u32 b0, b1, b2, b3;
                ldsm_x4t(b0, b1, b2, b3, brow + (u32)jt * 32);
                mma16816(acc[2 * jt], a0, a1, a2, a3, b0, b1);
                mma16816(acc[2 * jt + 1], a0, a1, a2, a3, b2, b3);
            }
        }

#pragma unroll
        for (int j = 0; j < 16; ++j) {
            acc[j][0] = fmaxf(acc[j][0], 0.f);
            acc[j][1] = fmaxf(acc[j][1], 0.f);
            acc[j][2] = fmaxf(acc[j][2], 0.f);
            acc[j][3] = fmaxf(acc[j][3], 0.f);
        }
        float s0 = 0.f, s1 = 0.f;
#pragma unroll
        for (int j = 0; j < 16; ++j) {
            s0 += acc[j][0] + acc[j][1];
            s1 += acc[j][2] + acc[j][3];
        }
        s0 += __shfl_xor_sync(0xFFFFFFFFu, s0, 1);
        s0 += __shfl_xor_sync(0xFFFFFFFFu, s0, 2);
        s1 += __shfl_xor_sync(0xFFFFFFFFu, s1, 1);
        s1 += __shfl_xor_sync(0xFFFFFFFFu, s1, 2);
        float mu0 = s0 * (1.f / 128.f);
        float mu1 = s1 * (1.f / 128.f);

        float v0 = 0.f, v1 = 0.f;
#pragma unroll
        for (int j = 0; j < 16; ++j) {
            float d0 = acc[j][0] - mu0, d1 = acc[j][1] - mu0;
            float d2 = acc[j][2] - mu1, d3 = acc[j][3] - mu1;
            v0 += d0 * d0 + d1 * d1;
            v1 += d2 * d2 + d3 * d3;
        }
        v0 += __shfl_xor_sync(0xFFFFFFFFu, v0, 1);
        v0 += __shfl_xor_sync(0xFFFFFFFFu, v0, 2);
        v1 += __shfl_xor_sync(0xFFFFFFFFu, v1, 1);
        v1 += __shfl_xor_sync(0xFFFFFFFFu, v1, 2);
        float rstd0 = rsqrtf(v0 * (1.f / 128.f) + 1e-5f);
        float rstd1 = rsqrtf(v1 * (1.f / 128.f) + 1e-5f);

        int r0 = node0 + wid * 16 + (lane >> 2);
        int r1 = r0 + 8;
        float mk0 = (r0 < NB) ? __ldg(&nmask[r0]) : 0.f;
        float mk1 = (r1 < NB) ? __ldg(&nmask[r1]) : 0.f;
        float a0s = rstd0 * mk0, a1s = rstd1 * mk1;

#pragma unroll
        for (int j = 0; j < 16; ++j) {
            int col = j * 8 + (lane & 3) * 2;
            float2 g2 = *(float2*)&gm_sm[col];
            float2 b2 = *(float2*)&bt_sm[col];
            if (r0 < NB) {
                float2 o;
                o.x = ((acc[j][0] - mu0) * g2.x * a0s) + b2.x * mk0;
                o.y = ((acc[j][1] - mu0) * g2.y * a0s) + b2.y * mk0;
                *(float2*)&out[(size_t)r0 * 128 + col] = o;
            }
            if (r1 < NB) {
                float2 o;
                o.x = ((acc[j][2] - mu1) * g2.x * a1s) + b2.x * mk1;
                o.y = ((acc[j][3] - mu1) * g2.y * a1s) + b2.y * mk1;
                *(float2*)&out[(size_t)r1 * 128 + col] = o;
            }
        }
        __syncthreads();
    }
}

// ---------------------------------------------------------------------------
// Launcher: stream-forked pipeline (graph-capturable event-fork pattern).
//   s1: zero_deg -> hist -> scan -> fill ......... fusedA .. fusedB
//   s0: conv (x->fp16) ............. gatherA .. gatherB
// FIX vs round 13: g_deg zeroing lives ON s1 BEFORE hist (was racing on s0).
// conv (pure x->fp16) has no shared state with the CSR chain.
// ---------------------------------------------------------------------------
extern "C" void kernel_launch(void* const* d_in, const int* in_sizes, int n_in,
                              void* d_out, int out_size) {
    const float* x     = (const float*)d_in[0];
    const int*   ei    = (const int*)d_in[1];
    const float* nmask = (const float*)d_in[2];
    const float* emask = (const float*)d_in[3];
    const float* Wself = (const float*)d_in[4];
    const float* bself = (const float*)d_in[5];
    const float* Wnb   = (const float*)d_in[6];
    const float* bnb   = (const float*)d_in[7];
    const float* gamma = (const float*)d_in[8];
    const float* beta  = (const float*)d_in[9];
    float* out = (float*)d_out;

    (void)in_sizes; (void)n_in; (void)out_size;

    static cudaStream_t s1 = nullptr;
    static cudaEvent_t evFork = nullptr, evFill = nullptr,
                       evA = nullptr, evB = nullptr, evEnd = nullptr;
    static bool attr_set = false;
    if (s1 == nullptr) {
        cudaStreamCreateWithFlags(&s1, cudaStreamNonBlocking);
        cudaEventCreateWithFlags(&evFork, cudaEventDisableTiming);
        cudaEventCreateWithFlags(&evFill, cudaEventDisableTiming);
        cudaEventCreateWithFlags(&evA, cudaEventDisableTiming);
        cudaEventCreateWithFlags(&evB, cudaEventDisableTiming);
        cudaEventCreateWithFlags(&evEnd, cudaEventDisableTiming);
    }
    if (!attr_set) {
        cudaFuncSetAttribute(fused_kernel,
                             cudaFuncAttributeMaxDynamicSharedMemorySize,
                             FUSED_SMEM_BYTES);
        attr_set = true;
    }

    const int nA = TSPLIT * 128;          // nodes covered by first pipe stage
    const cudaStream_t s0 = 0;            // default (capture) stream

    // fork
    cudaEventRecord(evFork, s0);
    cudaStreamWaitEvent(s1, evFork, 0);

    // s1: CSR build chain (zero_deg strictly before hist — same stream)
    zero_deg_kernel<<<(NB + 255) / 256, 256, 0, s1>>>();
    hist_kernel<<<(NE / 4 + 255) / 256, 256, 0, s1>>>(ei);
    scan_kernel<<<1, 1024, 0, s1>>>();
    fill_kernel<<<(NE / 4 + 255) / 256, 256, 0, s1>>>(ei, emask);
    cudaEventRecord(evFill, s1);

    // s0: x->fp16 conversion runs concurrently with CSR build (disjoint state)
    conv_kernel<<<(NB * DD / 4 + 255) / 256, 256, 0, s0>>>(x);

    // s0: gather A then B (need fill from s1; conv by program order on s0)
    cudaStreamWaitEvent(s0, evFill, 0);
    gather_kernel<<<(nA * 32 + 255) / 256, 256, 0, s0>>>(0, nA);
    cudaEventRecord(evA, s0);
    gather_kernel<<<((NB - nA) * 32 + 255) / 256, 256, 0, s0>>>(nA, NB);
    cudaEventRecord(evB, s0);

    // s1: fused A overlaps gather B; fused B after gather B
    cudaStreamWaitEvent(s1, evA, 0);
    fused_kernel<<<148, FUSED_THREADS, FUSED_SMEM_BYTES, s1>>>(
        Wself, bself, Wnb, bnb, gamma, beta, nmask, out, 0, TSPLIT);
    cudaStreamWaitEvent(s1, evB, 0);
    fused_kernel<<<148, FUSED_THREADS, FUSED_SMEM_BYTES, s1>>>(
        Wself, bself, Wnb, bnb, gamma, beta, nmask, out, TSPLIT, NTILES);

    // join back to the capture stream
    cudaEventRecord(evEnd, s1);
    cudaStreamWaitEvent(s0, evEnd, 0);
}

// round 15
// speedup vs baseline: 1.1742x; 1.1742x over previous
#include <cuda_runtime.h>
#include <cuda_fp16.h>

#define BB 8
#define NN 5000
#define EE 100000
#define DD 128
#define NB (BB * NN)        // 40000
#define NE (BB * EE)        // 800000

typedef unsigned long long u64;
typedef unsigned int u32;

// Scratch (allocation-free: __device__ globals)
__device__ __align__(16) int   g_deg[NB];
__device__ __align__(16) int   g_off[NB];
__device__ __align__(16) int   g_cursor[NB];
__device__ __align__(16) int2  g_bin[NE];
__device__ __align__(16) uint2 g_xh[NB * DD / 4];     // x as 4xhalf chunks
__device__ __align__(16) uint2 g_meanh[NB * DD / 4];  // mean as 4xhalf chunks

// ---------------------------------------------------------------------------
// K0: zero degree counters + convert x -> fp16
// ---------------------------------------------------------------------------
__global__ void prep_kernel(const float* __restrict__ x) {
    int i = blockIdx.x * blockDim.x + threadIdx.x;
    if (i < NB) g_deg[i] = 0;
    if (i < NB * DD / 4) {
        float4 v = __ldg(&((const float4*)x)[i]);
        __half2 h0 = __floats2half2_rn(v.x, v.y);
        __half2 h1 = __floats2half2_rn(v.z, v.w);
        g_xh[i] = make_uint2(*(u32*)&h0, *(u32*)&h1);
    }
}

// ---------------------------------------------------------------------------
// K1: histogram of edge targets (4 edges/thread)
// ---------------------------------------------------------------------------
__global__ void hist_kernel(const int* __restrict__ ei) {
    int t = blockIdx.x * blockDim.x + threadIdx.x;
    int base = t * 4;
    if (base >= NE) return;
    int b = base / EE;
    int e = base - b * EE;
    int4 t4 = __ldg((const int4*)&ei[(size_t)b * 2 * EE + EE + e]);
    int* deg = g_deg + b * NN;
    atomicAdd(&deg[t4.x], 1);
    atomicAdd(&deg[t4.y], 1);
    atomicAdd(&deg[t4.z], 1);
    atomicAdd(&deg[t4.w], 1);
}

// ---------------------------------------------------------------------------
// K2: exclusive prefix sum over 40000 degrees
// ---------------------------------------------------------------------------
__global__ void __launch_bounds__(1024, 1) scan_kernel() {
    __shared__ int part[1024];
    const int t = threadIdx.x;
    const int CH = 40;
    int lo = t * CH;
    if (lo < NB) {
        const int4* d4 = (const int4*)(g_deg + lo);
        int s = 0;
#pragma unroll
        for (int i = 0; i < CH / 4; ++i) {
            int4 v = d4[i];
            s += v.x + v.y + v.z + v.w;
        }
        part[t] = s;
    } else {
        part[t] = 0;
    }
    __syncthreads();

    for (int o = 1; o < 1024; o <<= 1) {
        int v = (t >= o) ? part[t - o] : 0;
        __syncthreads();
        part[t] += v;
        __syncthreads();
    }

    if (lo < NB) {
        int run = (t > 0) ? part[t - 1] : 0;
        const int4* d4 = (const int4*)(g_deg + lo);
        int4* o4 = (int4*)(g_off + lo);
        int4* c4 = (int4*)(g_cursor + lo);
#pragma unroll
        for (int i = 0; i < CH / 4; ++i) {
            int4 v = d4[i];
            int4 w;
            w.x = run; run += v.x;
            w.y = run; run += v.y;
            w.z = run; run += v.z;
            w.w = run; run += v.w;
            o4[i] = w;
            c4[i] = w;
        }
    }
}

// ---------------------------------------------------------------------------
// K3: fill bins (4 edges/thread)
// ---------------------------------------------------------------------------
__global__ void fill_kernel(const int* __restrict__ ei,
                            const float* __restrict__ em) {
    int t = blockIdx.x * blockDim.x + threadIdx.x;
    int base = t * 4;
    if (base >= NE) return;
    int b = base / EE;
    int e = base - b * EE;
    const int* eb = ei + (size_t)b * 2 * EE;
    int4 s4 = __ldg((const int4*)&eb[e]);
    int4 t4 = __ldg((const int4*)&eb[EE + e]);
    float4 m4 = __ldg((const float4*)&em[(size_t)b * EE + e]);
    int* cur = g_cursor + b * NN;
    int p0 = atomicAdd(&cur[t4.x], 1);
    int p1 = atomicAdd(&cur[t4.y], 1);
    int p2 = atomicAdd(&cur[t4.z], 1);
    int p3 = atomicAdd(&cur[t4.w], 1);
    g_bin[p0] = make_int2(s4.x, __float_as_int(m4.x));
    g_bin[p1] = make_int2(s4.y, __float_as_int(m4.y));
    g_bin[p2] = make_int2(s4.z, __float_as_int(m4.z));
    g_bin[p3] = make_int2(s4.w, __float_as_int(m4.w));
}

// ---------------------------------------------------------------------------
// K4: gather. One warp per node; lane owns uint2 (4 halfs) of the 256B row.
// 4-edge unroll. fp32 accum, fp16 mean out.
// ---------------------------------------------------------------------------
__global__ void gather_kernel() {
    int g = (blockIdx.x * blockDim.x + threadIdx.x) >> 5;
    int lane = threadIdx.x & 31;
    if (g >= NB) return;
    int b = g / NN;

    const int deg = g_deg[g];
    const int off = g_off[g];
    const uint2* xr = g_xh + (size_t)b * NN * 32;
    const int2* bin = g_bin + off;

    float4 acc = make_float4(0.f, 0.f, 0.f, 0.f);
    float cm = 0.f;

#define EDGE_FMA(u, m)                                                        \
    {                                                                         \
        float2 a = __half22float2(*(__half2*)&(u).x);                         \
        float2 c = __half22float2(*(__half2*)&(u).y);                         \
        acc.x = fmaf(a.x, (m), acc.x);                                        \
        acc.y = fmaf(a.y, (m), acc.y);                                        \
        acc.z = fmaf(c.x, (m), acc.z);                                        \
        acc.w = fmaf(c.y, (m), acc.w);                                        \
        cm += (m);                                                            \
    }

    int j = 0;
    for (; j + 4 <= deg; j += 4) {
        int2 r0 = __ldg(&bin[j]);
        int2 r1 = __ldg(&bin[j + 1]);
        int2 r2 = __ldg(&bin[j + 2]);
        int2 r3 = __ldg(&bin[j + 3]);
        uint2 u0 = __ldg(&xr[(size_t)r0.x * 32 + lane]);
        uint2 u1 = __ldg(&xr[(size_t)r1.x * 32 + lane]);
        uint2 u2 = __ldg(&xr[(size_t)r2.x * 32 + lane]);
        uint2 u3 = __ldg(&xr[(size_t)r3.x * 32 + lane]);
        EDGE_FMA(u0, __int_as_float(r0.y))
        EDGE_FMA(u1, __int_as_float(r1.y))
        EDGE_FMA(u2, __int_as_float(r2.y))
        EDGE_FMA(u3, __int_as_float(r3.y))
    }
    for (; j < deg; ++j) {
        int2 r = __ldg(&bin[j]);
        uint2 u = __ldg(&xr[(size_t)r.x * 32 + lane]);
        EDGE_FMA(u, __int_as_float(r.y))
    }
#undef EDGE_FMA

    float inv = 1.f / fmaxf(cm, 1.f);
    __half2 h0 = __floats2half2_rn(acc.x * inv, acc.y * inv);
    __half2 h1 = __floats2half2_rn(acc.z * inv, acc.w * inv);
    g_meanh[(size_t)g * 32 + lane] = make_uint2(*(u32*)&h0, *(u32*)&h1);
}

// ---------------------------------------------------------------------------
// K5: fused HMMA GEMM + relu + LN + mask.
// A = [x || mean] fp16 (k=256), B = [Wself ; Wnb] fp16 (k=256, n=128).
// Block: 256 threads = 8 warps. Warp owns 16 nodes x 128 cols.
// Tile = 128 nodes. fp32 accum, bias folded in. Conflict-free ldmatrix pitches.
// ---------------------------------------------------------------------------
#define FUSED_THREADS 256
#define IN_PITCH 264
#define W_PITCH_H 136
#define SMEM_WH_BYTES (256 * W_PITCH_H * 2)
#define SMEM_IN_BYTES (128 * IN_PITCH * 2)
#define SMEM_CONST_BYTES (3 * 128 * 4)
#define FUSED_SMEM_BYTES (SMEM_WH_BYTES + SMEM_IN_BYTES + SMEM_CONST_BYTES)
#define NTILES ((NB + 127) / 128)             // 313

__device__ __forceinline__ u32 smem_u32(const void* p) {
    u32 a;
    asm("{ .reg .u64 t; cvta.to.shared.u64 t, %1; cvt.u32.u64 %0, t; }"
        : "=r"(a) : "l"(p));
    return a;
}
__device__ __forceinline__ void ldsm_x4(u32& r0, u32& r1, u32& r2, u32& r3, u32 a) {
    asm volatile("ldmatrix.sync.aligned.m8n8.x4.shared.b16 {%0,%1,%2,%3}, [%4];"
                 : "=r"(r0), "=r"(r1), "=r"(r2), "=r"(r3) : "r"(a));
}
__device__ __forceinline__ void ldsm_x4t(u32& r0, u32& r1, u32& r2, u32& r3, u32 a) {
    asm volatile("ldmatrix.sync.aligned.m8n8.x4.trans.shared.b16 {%0,%1,%2,%3}, [%4];"
                 : "=r"(r0), "=r"(r1), "=r"(r2), "=r"(r3) : "r"(a));
}
__device__ __forceinline__ void mma16816(float* c, u32 a0, u32 a1, u32 a2, u32 a3,
                                         u32 b0, u32 b1) {
    asm volatile(
        "mma.sync.aligned.m16n8k16.row.col.f32.f16.f16.f32 "
        "{%0,%1,%2,%3}, {%4,%5,%6,%7}, {%8,%9}, {%0,%1,%2,%3};"
        : "+f"(c[0]), "+f"(c[1]), "+f"(c[2]), "+f"(c[3])
        : "r"(a0), "r"(a1), "r"(a2), "r"(a3), "r"(b0), "r"(b1));
}

__global__ void __launch_bounds__(FUSED_THREADS, 1)
fused_kernel(const float* __restrict__ Wself,
             const float* __restrict__ bself,
             const float* __restrict__ Wnb,
             const float* __restrict__ bnb,
             const float* __restrict__ gamma,
             const float* __restrict__ beta,
             const float* __restrict__ nmask,
             float* __restrict__ out) {
    extern __shared__ char sm[];
    __half* Wh = (__half*)sm;
    __half* inSh = (__half*)(sm + SMEM_WH_BYTES);
    float* bias_sm = (float*)(sm + SMEM_WH_BYTES + SMEM_IN_BYTES);
    float* gm_sm = bias_sm + 128;
    float* bt_sm = gm_sm + 128;

    const int tid = threadIdx.x;
    const int lane = tid & 31;
    const int wid = tid >> 5;

    for (int i = tid; i < 256 * 128; i += FUSED_THREADS) {
        int k = i >> 7;
        int n = i & 127;
        float w = (k < 128) ? __ldg(&Wself[k * 128 + n])
                            : __ldg(&Wnb[(k - 128) * 128 + n]);
        Wh[k * W_PITCH_H + n] = __float2half_rn(w);
    }
    if (tid < 128) {
        bias_sm[tid] = __ldg(&bself[tid]) + __ldg(&bnb[tid]);
        gm_sm[tid] = __ldg(&gamma[tid]);
        bt_sm[tid] = __ldg(&beta[tid]);
    }
    __syncthreads();

    const u32 in_u = smem_u32(inSh);
    const u32 wh_u = smem_u32(Wh);
    const u32 a_row_off = (u32)(wid * 16 + (lane & 15)) * (IN_PITCH * 2)
                        + (u32)((lane >> 4) * 8) * 2;
    const u32 b_row_lane = (u32)(lane & 15) * (W_PITCH_H * 2);
    const u32 b_col_lane = (u32)((lane >> 4) * 8) * 2;

    for (int tile = blockIdx.x; tile < NTILES; tile += gridDim.x) {
        const int node0 = tile * 128;

        for (int i = tid; i < 128 * 64; i += FUSED_THREADS) {
            int nl = i >> 6;
            int c = i & 63;
            int gn = node0 + nl;
            uint2 v = make_uint2(0u, 0u);
            if (gn < NB)
                v = (c < 32) ? __ldg(&g_xh[(size_t)gn * 32 + c])
                             : __ldg(&g_meanh[(size_t)gn * 32 + (c - 32)]);
            *(uint2*)((char*)inSh + (size_t)nl * (IN_PITCH * 2) + (size_t)c * 8) = v;
        }
        __syncthreads();

        float acc[16][4];
#pragma unroll
        for (int j = 0; j < 16; ++j) {
            float2 bv = *(float2*)&bias_sm[j * 8 + (lane & 3) * 2];
            acc[j][0] = bv.x; acc[j][1] = bv.y;
            acc[j][2] = bv.x; acc[j][3] = bv.y;
        }

#pragma unroll 1
        for (int ks = 0; ks < 16; ++ks) {
            u32 a0, a1, a2, a3;
            ldsm_x4(a0, a1, a2, a3, in_u + a_row_off + (u32)ks * 32);
            u32 brow = wh_u + (u32)ks * 16 * (W_PITCH_H * 2) + b_row_lane + b_col_lane;
#pragma unroll
            for (int jt = 0; jt < 8; ++jt) {
                u32 b0, b1, b2, b3;
                ldsm_x4t(b0, b1, b2, b3, brow + (u32)jt * 32);
                mma16816(acc[2 * jt], a0, a1, a2, a3, b0, b1);
                mma16816(acc[2 * jt + 1], a0, a1, a2, a3, b2, b3);
            }
        }

#pragma unroll
        for (int j = 0; j < 16; ++j) {
            acc[j][0] = fmaxf(acc[j][0], 0.f);
            acc[j][1] = fmaxf(acc[j][1], 0.f);
            acc[j][2] = fmaxf(acc[j][2], 0.f);
            acc[j][3] = fmaxf(acc[j][3], 0.f);
        }
        float s0 = 0.f, s1 = 0.f;
#pragma unroll
        for (int j = 0; j < 16; ++j) {
            s0 += acc[j][0] + acc[j][1];
            s1 += acc[j][2] + acc[j][3];
        }
        s0 += __shfl_xor_sync(0xFFFFFFFFu, s0, 1);
        s0 += __shfl_xor_sync(0xFFFFFFFFu, s0, 2);
        s1 += __shfl_xor_sync(0xFFFFFFFFu, s1, 1);
        s1 += __shfl_xor_sync(0xFFFFFFFFu, s1, 2);
        float mu0 = s0 * (1.f / 128.f);
        float mu1 = s1 * (1.f / 128.f);

        float v0 = 0.f, v1 = 0.f;
#pragma unroll
        for (int j = 0; j < 16; ++j) {
            float d0 = acc[j][0] - mu0, d1 = acc[j][1] - mu0;
            float d2 = acc[j][2] - mu1, d3 = acc[j][3] - mu1;
            v0 += d0 * d0 + d1 * d1;
            v1 += d2 * d2 + d3 * d3;
        }
        v0 += __shfl_xor_sync(0xFFFFFFFFu, v0, 1);
        v0 += __shfl_xor_sync(0xFFFFFFFFu, v0, 2);
        v1 += __shfl_xor_sync(0xFFFFFFFFu, v1, 1);
        v1 += __shfl_xor_sync(0xFFFFFFFFu, v1, 2);
        float rstd0 = rsqrtf(v0 * (1.f / 128.f) + 1e-5f);
        float rstd1 = rsqrtf(v1 * (1.f / 128.f) + 1e-5f);

        int r0 = node0 + wid * 16 + (lane >> 2);
        int r1 = r0 + 8;
        float mk0 = (r0 < NB) ? __ldg(&nmask[r0]) : 0.f;
        float mk1 = (r1 < NB) ? __ldg(&nmask[r1]) : 0.f;
        float a0s = rstd0 * mk0, a1s = rstd1 * mk1;

#pragma unroll
        for (int j = 0; j < 16; ++j) {
            int col = j * 8 + (lane & 3) * 2;
            float2 g2 = *(float2*)&gm_sm[col];
            float2 b2 = *(float2*)&bt_sm[col];
            if (r0 < NB) {
                float2 o;
                o.x = ((acc[j][0] - mu0) * g2.x * a0s) + b2.x * mk0;
                o.y = ((acc[j][1] - mu0) * g2.y * a0s) + b2.y * mk0;
                *(float2*)&out[(size_t)r0 * 128 + col] = o;
            }
            if (r1 < NB) {
                float2 o;
                o.x = ((acc[j][2] - mu1) * g2.x * a1s) + b2.x * mk1;
                o.y = ((acc[j][3] - mu1) * g2.y * a1s) + b2.y * mk1;
                *(float2*)&out[(size_t)r1 * 128 + col] = o;
            }
        }
        __syncthreads();
    }
}

// ---------------------------------------------------------------------------
extern "C" void kernel_launch(void* const* d_in, const int* in_sizes, int n_in,
                              void* d_out, int out_size) {
    const float* x     = (const float*)d_in[0];
    const int*   ei    = (const int*)d_in[1];
    const float* nmask = (const float*)d_in[2];
    const float* emask = (const float*)d_in[3];
    const float* Wself = (const float*)d_in[4];
    const float* bself = (const float*)d_in[5];
    const float* Wnb   = (const float*)d_in[6];
    const float* bnb   = (const float*)d_in[7];
    const float* gamma = (const float*)d_in[8];
    const float* beta  = (const float*)d_in[9];
    float* out = (float*)d_out;

    (void)in_sizes; (void)n_in; (void)out_size;

    prep_kernel<<<(NB * DD / 4 + 255) / 256, 256>>>(x);
    hist_kernel<<<(NE / 4 + 255) / 256, 256>>>(ei);
    scan_kernel<<<1, 1024>>>();
    fill_kernel<<<(NE / 4 + 255) / 256, 256>>>(ei, emask);
    gather_kernel<<<(NB * 32 + 255) / 256, 256>>>();

    cudaFuncSetAttribute(fused_kernel, cudaFuncAttributeMaxDynamicSharedMemorySize,
                         FUSED_SMEM_BYTES);
    int nsm = 148;
    cudaDeviceGetAttribute(&nsm, cudaDevAttrMultiProcessorCount, 0);
    fused_kernel<<<nsm, FUSED_THREADS, FUSED_SMEM_BYTES>>>(
        Wself, bself, Wnb, bnb, gamma, beta, nmask, out);
}

// round 16
// speedup vs baseline: 1.2163x; 1.0359x over previous
#include <cuda_runtime.h>
#include <cuda_fp16.h>

#define BB 8
#define NN 5000
#define EE 100000
#define DD 128
#define NB (BB * NN)        // 40000
#define NE (BB * EE)        // 800000

typedef unsigned long long u64;
typedef unsigned int u32;

// Scratch (allocation-free: __device__ globals)
__device__ __align__(16) int   g_deg[NB];
__device__ __align__(16) int   g_off[NB];
__device__ __align__(16) int   g_cursor[NB];
__device__ __align__(16) int2  g_bin[NE];
__device__ __align__(16) uint2 g_xh[NB * DD / 4];     // x as 4xhalf chunks
__device__ __align__(16) uint2 g_meanh[NB * DD / 4];  // mean as 4xhalf chunks

// ---------------------------------------------------------------------------
// K0: zero degree counters + convert x -> fp16   (round-5 proven)
// ---------------------------------------------------------------------------
__global__ void prep_kernel(const float* __restrict__ x) {
    int i = blockIdx.x * blockDim.x + threadIdx.x;
    if (i < NB) g_deg[i] = 0;
    if (i < NB * DD / 4) {
        float4 v = __ldg(&((const float4*)x)[i]);
        __half2 h0 = __floats2half2_rn(v.x, v.y);
        __half2 h1 = __floats2half2_rn(v.z, v.w);
        g_xh[i] = make_uint2(*(u32*)&h0, *(u32*)&h1);
    }
}

// ---------------------------------------------------------------------------
// K1: histogram of edge targets (4 edges/thread)   (round-5 proven)
// ---------------------------------------------------------------------------
__global__ void hist_kernel(const int* __restrict__ ei) {
    int t = blockIdx.x * blockDim.x + threadIdx.x;
    int base = t * 4;
    if (base >= NE) return;
    int b = base / EE;
    int e = base - b * EE;
    int4 t4 = __ldg((const int4*)&ei[(size_t)b * 2 * EE + EE + e]);
    int* deg = g_deg + b * NN;
    atomicAdd(&deg[t4.x], 1);
    atomicAdd(&deg[t4.y], 1);
    atomicAdd(&deg[t4.z], 1);
    atomicAdd(&deg[t4.w], 1);
}

// ---------------------------------------------------------------------------
// K2: exclusive prefix sum over 40000 degrees   (round-5 proven)
// ---------------------------------------------------------------------------
__global__ void __launch_bounds__(1024, 1) scan_kernel() {
    __shared__ int part[1024];
    const int t = threadIdx.x;
    const int CH = 40;
    int lo = t * CH;
    if (lo < NB) {
        const int4* d4 = (const int4*)(g_deg + lo);
        int s = 0;
#pragma unroll
        for (int i = 0; i < CH / 4; ++i) {
            int4 v = d4[i];
            s += v.x + v.y + v.z + v.w;
        }
        part[t] = s;
    } else {
        part[t] = 0;
    }
    __syncthreads();

    for (int o = 1; o < 1024; o <<= 1) {
        int v = (t >= o) ? part[t - o] : 0;
        __syncthreads();
        part[t] += v;
        __syncthreads();
    }

    if (lo < NB) {
        int run = (t > 0) ? part[t - 1] : 0;
        const int4* d4 = (const int4*)(g_deg + lo);
        int4* o4 = (int4*)(g_off + lo);
        int4* c4 = (int4*)(g_cursor + lo);
#pragma unroll
        for (int i = 0; i < CH / 4; ++i) {
            int4 v = d4[i];
            int4 w;
            w.x = run; run += v.x;
            w.y = run; run += v.y;
            w.z = run; run += v.z;
            w.w = run; run += v.w;
            o4[i] = w;
            c4[i] = w;
        }
    }
}

// ---------------------------------------------------------------------------
// K3: fill bins (8 edges/thread — round-6 measured 17.0us vs 18.3 at 4)
// ---------------------------------------------------------------------------
__global__ void fill_kernel(const int* __restrict__ ei,
                            const float* __restrict__ em) {
    int t = blockIdx.x * blockDim.x + threadIdx.x;
    int base = t * 8;
    if (base >= NE) return;
    int b = base / EE;
    int e = base - b * EE;
    const int* eb = ei + (size_t)b * 2 * EE;
    int4 sa = __ldg((const int4*)&eb[e]);
    int4 sb = __ldg((const int4*)&eb[e + 4]);
    int4 ta = __ldg((const int4*)&eb[EE + e]);
    int4 tb = __ldg((const int4*)&eb[EE + e + 4]);
    float4 ma = __ldg((const float4*)&em[(size_t)b * EE + e]);
    float4 mb = __ldg((const float4*)&em[(size_t)b * EE + e + 4]);
    int* cur = g_cursor + b * NN;
    int p0 = atomicAdd(&cur[ta.x], 1);
    int p1 = atomicAdd(&cur[ta.y], 1);
    int p2 = atomicAdd(&cur[ta.z], 1);
    int p3 = atomicAdd(&cur[ta.w], 1);
    int p4 = atomicAdd(&cur[tb.x], 1);
    int p5 = atomicAdd(&cur[tb.y], 1);
    int p6 = atomicAdd(&cur[tb.z], 1);
    int p7 = atomicAdd(&cur[tb.w], 1);
    g_bin[p0] = make_int2(sa.x, __float_as_int(ma.x));
    g_bin[p1] = make_int2(sa.y, __float_as_int(ma.y));
    g_bin[p2] = make_int2(sa.z, __float_as_int(ma.z));
    g_bin[p3] = make_int2(sa.w, __float_as_int(ma.w));
    g_bin[p4] = make_int2(sb.x, __float_as_int(mb.x));
    g_bin[p5] = make_int2(sb.y, __float_as_int(mb.y));
    g_bin[p6] = make_int2(sb.z, __float_as_int(mb.z));
    g_bin[p7] = make_int2(sb.w, __float_as_int(mb.w));
}

// ---------------------------------------------------------------------------
// K4: gather — round-5 proven inner loop, launched as 64-thread (2-warp)
// blocks. 256-thread blocks capped residency at 7 blocks/SM (reg-file
// granularity: 34 regs x 256 thr) -> 56 warps theoretical, 61% measured.
// 2-warp blocks: HW cap 32 blocks/SM, regs allow 30 -> ~60-64 resident warps
// (~100% occupancy) + finer scheduling granularity absorbs degree variance.
// ---------------------------------------------------------------------------
#define GATHER_TPB 64

__global__ void __launch_bounds__(GATHER_TPB) gather_kernel() {
    int g = (blockIdx.x * blockDim.x + threadIdx.x) >> 5;
    int lane = threadIdx.x & 31;
    if (g >= NB) return;
    int b = g / NN;

    const int deg = g_deg[g];
    const int off = g_off[g];
    const uint2* xr = g_xh + (size_t)b * NN * 32;
    const int2* bin = g_bin + off;

    float4 acc = make_float4(0.f, 0.f, 0.f, 0.f);
    float cm = 0.f;

#define EDGE_FMA(u, m)                                                        \
    {                                                                         \
        float2 a = __half22float2(*(__half2*)&(u).x);                         \
        float2 c = __half22float2(*(__half2*)&(u).y);                         \
        acc.x = fmaf(a.x, (m), acc.x);                                        \
        acc.y = fmaf(a.y, (m), acc.y);                                        \
        acc.z = fmaf(c.x, (m), acc.z);                                        \
        acc.w = fmaf(c.y, (m), acc.w);                                        \
        cm += (m);                                                            \
    }

    int j = 0;
    for (; j + 4 <= deg; j += 4) {
        int2 r0 = __ldg(&bin[j]);
        int2 r1 = __ldg(&bin[j + 1]);
        int2 r2 = __ldg(&bin[j + 2]);
        int2 r3 = __ldg(&bin[j + 3]);
        uint2 u0 = __ldg(&xr[(size_t)r0.x * 32 + lane]);
        uint2 u1 = __ldg(&xr[(size_t)r1.x * 32 + lane]);
        uint2 u2 = __ldg(&xr[(size_t)r2.x * 32 + lane]);
        uint2 u3 = __ldg(&xr[(size_t)r3.x * 32 + lane]);
        EDGE_FMA(u0, __int_as_float(r0.y))
        EDGE_FMA(u1, __int_as_float(r1.y))
        EDGE_FMA(u2, __int_as_float(r2.y))
        EDGE_FMA(u3, __int_as_float(r3.y))
    }
    for (; j < deg; ++j) {
        int2 r = __ldg(&bin[j]);
        uint2 u = __ldg(&xr[(size_t)r.x * 32 + lane]);
        EDGE_FMA(u, __int_as_float(r.y))
    }
#undef EDGE_FMA

    float inv = 1.f / fmaxf(cm, 1.f);
    __half2 h0 = __floats2half2_rn(acc.x * inv, acc.y * inv);
    __half2 h1 = __floats2half2_rn(acc.z * inv, acc.w * inv);
    g_meanh[(size_t)g * 32 + lane] = make_uint2(*(u32*)&h0, *(u32*)&h1);
}

// ---------------------------------------------------------------------------
// K5: fused HMMA GEMM + relu + LN + mask (unchanged from round 5).
// ---------------------------------------------------------------------------
#define FUSED_THREADS 256
#define IN_PITCH 264
#define W_PITCH_H 136
#define SMEM_WH_BYTES (256 * W_PITCH_H * 2)
#define SMEM_IN_BYTES (128 * IN_PITCH * 2)
#define SMEM_CONST_BYTES (3 * 128 * 4)
#define FUSED_SMEM_BYTES (SMEM_WH_BYTES + SMEM_IN_BYTES + SMEM_CONST_BYTES)
#define NTILES ((NB + 127) / 128)             // 313

__device__ __forceinline__ u32 smem_u32(const void* p) {
    u32 a;
    asm("{ .reg .u64 t; cvta.to.shared.u64 t, %1; cvt.u32.u64 %0, t; }"
        : "=r"(a) : "l"(p));
    return a;
}
__device__ __forceinline__ void ldsm_x4(u32& r0, u32& r1, u32& r2, u32& r3, u32 a) {
    asm volatile("ldmatrix.sync.aligned.m8n8.x4.shared.b16 {%0,%1,%2,%3}, [%4];"
                 : "=r"(r0), "=r"(r1), "=r"(r2), "=r"(r3) : "r"(a));
}
__device__ __forceinline__ void ldsm_x4t(u32& r0, u32& r1, u32& r2, u32& r3, u32 a) {
    asm volatile("ldmatrix.sync.aligned.m8n8.x4.trans.shared.b16 {%0,%1,%2,%3}, [%4];"
                 : "=r"(r0), "=r"(r1), "=r"(r2), "=r"(r3) : "r"(a));
}
__device__ __forceinline__ void mma16816(float* c, u32 a0, u32 a1, u32 a2, u32 a3,
                                         u32 b0, u32 b1) {
    asm volatile(
        "mma.sync.aligned.m16n8k16.row.col.f32.f16.f16.f32 "
        "{%0,%1,%2,%3}, {%4,%5,%6,%7}, {%8,%9}, {%0,%1,%2,%3};"
        : "+f"(c[0]), "+f"(c[1]), "+f"(c[2]), "+f"(c[3])
        : "r"(a0), "r"(a1), "r"(a2), "r"(a3), "r"(b0), "r"(b1));
}

__global__ void __launch_bounds__(FUSED_THREADS, 1)
fused_kernel(const float* __restrict__ Wself,
             const float* __restrict__ bself,
             const float* __restrict__ Wnb,
             const float* __restrict__ bnb,
             const float* __restrict__ gamma,
             const float* __restrict__ beta,
             const float* __restrict__ nmask,
             float* __restrict__ out) {
    extern __shared__ char sm[];
    __half* Wh = (__half*)sm;
    __half* inSh = (__half*)(sm + SMEM_WH_BYTES);
    float* bias_sm = (float*)(sm + SMEM_WH_BYTES + SMEM_IN_BYTES);
    float* gm_sm = bias_sm + 128;
    float* bt_sm = gm_sm + 128;

    const int tid = threadIdx.x;
    const int lane = tid & 31;
    const int wid = tid >> 5;

    for (int i = tid; i < 256 * 128; i += FUSED_THREADS) {
        int k = i >> 7;
        int n = i & 127;
        float w = (k < 128) ? __ldg(&Wself[k * 128 + n])
                            : __ldg(&Wnb[(k - 128) * 128 + n]);
        Wh[k * W_PITCH_H + n] = __float2half_rn(w);
    }
    if (tid < 128) {
        bias_sm[tid] = __ldg(&bself[tid]) + __ldg(&bnb[tid]);
        gm_sm[tid] = __ldg(&gamma[tid]);
        bt_sm[tid] = __ldg(&beta[tid]);
    }
    __syncthreads();

    const u32 in_u = smem_u32(inSh);
    const u32 wh_u = smem_u32(Wh);
    const u32 a_row_off = (u32)(wid * 16 + (lane & 15)) * (IN_PITCH * 2)
                        + (u32)((lane >> 4) * 8) * 2;
    const u32 b_row_lane = (u32)(lane & 15) * (W_PITCH_H * 2);
    const u32 b_col_lane = (u32)((lane >> 4) * 8) * 2;

    for (int tile = blockIdx.x; tile < NTILES; tile += gridDim.x) {
        const int node0 = tile * 128;

        for (int i = tid; i < 128 * 64; i += FUSED_THREADS) {
            int nl = i >> 6;
            int c = i & 63;
            int gn = node0 + nl;
            uint2 v = make_uint2(0u, 0u);
            if (gn < NB)
                v = (c < 32) ? __ldg(&g_xh[(size_t)gn * 32 + c])
                             : __ldg(&g_meanh[(size_t)gn * 32 + (c - 32)]);
            *(uint2*)((char*)inSh + (size_t)nl * (IN_PITCH * 2) + (size_t)c * 8) = v;
        }
        __syncthreads();

        float acc[16][4];
#pragma unroll
        for (int j = 0; j < 16; ++j) {
            float2 bv = *(float2*)&bias_sm[j * 8 + (lane & 3) * 2];
            acc[j][0] = bv.x; acc[j][1] = bv.y;
            acc[j][2] = bv.x; acc[j][3] = bv.y;
        }

#pragma unroll 1
        for (int ks = 0; ks < 16; ++ks) {
            u32 a0, a1, a2, a3;
            ldsm_x4(a0, a1, a2, a3, in_u + a_row_off + (u32)ks * 32);
            u32 brow = wh_u + (u32)ks * 16 * (W_PITCH_H * 2) + b_row_lane + b_col_lane;
#pragma unroll
            for (int jt = 0; jt < 8; ++jt) {
                u32 b0, b1, b2, b3;
                ldsm_x4t(b0, b1, b2, b3, brow + (u32)jt * 32);
                mma16816(acc[2 * jt], a0, a1, a2, a3, b0, b1);
                mma16816(acc[2 * jt + 1], a0, a1, a2, a3, b2, b3);
            }
        }

#pragma unroll
        for (int j = 0; j < 16; ++j) {
            acc[j][0] = fmaxf(acc[j][0], 0.f);
            acc[j][1] = fmaxf(acc[j][1], 0.f);
            acc[j][2] = fmaxf(acc[j][2], 0.f);
            acc[j][3] = fmaxf(acc[j][3], 0.f);
        }
        float s0 = 0.f, s1 = 0.f;
#pragma unroll
        for (int j = 0; j < 16; ++j) {
            s0 += acc[j][0] + acc[j][1];
            s1 += acc[j][2] + acc[j][3];
        }
        s0 += __shfl_xor_sync(0xFFFFFFFFu, s0, 1);
        s0 += __shfl_xor_sync(0xFFFFFFFFu, s0, 2);
        s1 += __shfl_xor_sync(0xFFFFFFFFu, s1, 1);
        s1 += __shfl_xor_sync(0xFFFFFFFFu, s1, 2);
        float mu0 = s0 * (1.f / 128.f);
        float mu1 = s1 * (1.f / 128.f);

        float v0 = 0.f, v1 = 0.f;
#pragma unroll
        for (int j = 0; j < 16; ++j) {
            float d0 = acc[j][0] - mu0, d1 = acc[j][1] - mu0;
            float d2 = acc[j][2] - mu1, d3 = acc[j][3] - mu1;
            v0 += d0 * d0 + d1 * d1;
            v1 += d2 * d2 + d3 * d3;
        }
        v0 += __shfl_xor_sync(0xFFFFFFFFu, v0, 1);
        v0 += __shfl_xor_sync(0xFFFFFFFFu, v0, 2);
        v1 += __shfl_xor_sync(0xFFFFFFFFu, v1, 1);
        v1 += __shfl_xor_sync(0xFFFFFFFFu, v1, 2);
        float rstd0 = rsqrtf(v0 * (1.f / 128.f) + 1e-5f);
        float rstd1 = rsqrtf(v1 * (1.f / 128.f) + 1e-5f);

        int r0 = node0 + wid * 16 + (lane >> 2);
        int r1 = r0 + 8;
        float mk0 = (r0 < NB) ? __ldg(&nmask[r0]) : 0.f;
        float mk1 = (r1 < NB) ? __ldg(&nmask[r1]) : 0.f;
        float a0s = rstd0 * mk0, a1s = rstd1 * mk1;

#pragma unroll
        for (int j = 0; j < 16; ++j) {
            int col = j * 8 + (lane & 3) * 2;
            float2 g2 = *(float2*)&gm_sm[col];
            float2 b2 = *(float2*)&bt_sm[col];
            if (r0 < NB) {
                float2 o;
                o.x = ((acc[j][0] - mu0) * g2.x * a0s) + b2.x * mk0;
                o.y = ((acc[j][1] - mu0) * g2.y * a0s) + b2.y * mk0;
                *(float2*)&out[(size_t)r0 * 128 + col] = o;
            }
            if (r1 < NB) {
                float2 o;
                o.x = ((acc[j][2] - mu1) * g2.x * a1s) + b2.x * mk1;
                o.y = ((acc[j][3] - mu1) * g2.y * a1s) + b2.y * mk1;
                *(float2*)&out[(size_t)r1 * 128 + col] = o;
            }
        }
        __syncthreads();
    }
}

// ---------------------------------------------------------------------------
extern "C" void kernel_launch(void* const* d_in, const int* in_sizes, int n_in,
                              void* d_out, int out_size) {
    const float* x     = (const float*)d_in[0];
    const int*   ei    = (const int*)d_in[1];
    const float* nmask = (const float*)d_in[2];
    const float* emask = (const float*)d_in[3];
    const float* Wself = (const float*)d_in[4];
    const float* bself = (const float*)d_in[5];
    const float* Wnb   = (const float*)d_in[6];
    const float* bnb   = (const float*)d_in[7];
    const float* gamma = (const float*)d_in[8];
    const float* beta  = (const float*)d_in[9];
    float* out = (float*)d_out;

    (void)in_sizes; (void)n_in; (void)out_size;

    prep_kernel<<<(NB * DD / 4 + 255) / 256, 256>>>(x);
    hist_kernel<<<(NE / 4 + 255) / 256, 256>>>(ei);
    scan_kernel<<<1, 1024>>>();
    fill_kernel<<<(NE / 8 + 255) / 256, 256>>>(ei, emask);
    gather_kernel<<<(NB * 32 + GATHER_TPB - 1) / GATHER_TPB, GATHER_TPB>>>();

    cudaFuncSetAttribute(fused_kernel, cudaFuncAttributeMaxDynamicSharedMemorySize,
                         FUSED_SMEM_BYTES);
    int nsm = 148;
    cudaDeviceGetAttribute(&nsm, cudaDevAttrMultiProcessorCount, 0);
    fused_kernel<<<nsm, FUSED_THREADS, FUSED_SMEM_BYTES>>>(
        Wself, bself, Wnb, bnb, gamma, beta, nmask, out);
}

// round 17
// speedup vs baseline: 1.2195x; 1.0026x over previous
#include <cuda_runtime.h>
#include <cuda_fp16.h>

#define BB 8
#define NN 5000
#define EE 100000
#define DD 128
#define NB (BB * NN)        // 40000
#define NE (BB * EE)        // 800000

typedef unsigned long long u64;
typedef unsigned int u32;

// Scratch (allocation-free: __device__ globals)
__device__ __align__(16) int   g_deg[NB];
__device__ __align__(16) int   g_off[NB];
__device__ __align__(16) int   g_cursor[NB];
__device__ __align__(16) int2  g_bin[NE];
__device__ __align__(16) uint2 g_xh[NB * DD / 4];     // x as 4xhalf chunks
__device__ __align__(16) uint2 g_meanh[NB * DD / 4];  // mean as 4xhalf chunks

// ---------------------------------------------------------------------------
// K0: zero degree counters + convert x -> fp16
// ---------------------------------------------------------------------------
__global__ void prep_kernel(const float* __restrict__ x) {
    int i = blockIdx.x * blockDim.x + threadIdx.x;
    if (i < NB) g_deg[i] = 0;
    if (i < NB * DD / 4) {
        float4 v = __ldg(&((const float4*)x)[i]);
        __half2 h0 = __floats2half2_rn(v.x, v.y);
        __half2 h1 = __floats2half2_rn(v.z, v.w);
        g_xh[i] = make_uint2(*(u32*)&h0, *(u32*)&h1);
    }
}

// ---------------------------------------------------------------------------
// K1: histogram of edge targets (4 edges/thread)
// ---------------------------------------------------------------------------
__global__ void hist_kernel(const int* __restrict__ ei) {
    int t = blockIdx.x * blockDim.x + threadIdx.x;
    int base = t * 4;
    if (base >= NE) return;
    int b = base / EE;
    int e = base - b * EE;
    int4 t4 = __ldg((const int4*)&ei[(size_t)b * 2 * EE + EE + e]);
    int* deg = g_deg + b * NN;
    atomicAdd(&deg[t4.x], 1);
    atomicAdd(&deg[t4.y], 1);
    atomicAdd(&deg[t4.z], 1);
    atomicAdd(&deg[t4.w], 1);
}

// ---------------------------------------------------------------------------
// K2: exclusive prefix sum over 40000 degrees
// ---------------------------------------------------------------------------
__global__ void __launch_bounds__(1024, 1) scan_kernel() {
    __shared__ int part[1024];
    const int t = threadIdx.x;
    const int CH = 40;
    int lo = t * CH;
    if (lo < NB) {
        const int4* d4 = (const int4*)(g_deg + lo);
        int s = 0;
#pragma unroll
        for (int i = 0; i < CH / 4; ++i) {
            int4 v = d4[i];
            s += v.x + v.y + v.z + v.w;
        }
        part[t] = s;
    } else {
        part[t] = 0;
    }
    __syncthreads();

    for (int o = 1; o < 1024; o <<= 1) {
        int v = (t >= o) ? part[t - o] : 0;
        __syncthreads();
        part[t] += v;
        __syncthreads();
    }

    if (lo < NB) {
        int run = (t > 0) ? part[t - 1] : 0;
        const int4* d4 = (const int4*)(g_deg + lo);
        int4* o4 = (int4*)(g_off + lo);
        int4* c4 = (int4*)(g_cursor + lo);
#pragma unroll
        for (int i = 0; i < CH / 4; ++i) {
            int4 v = d4[i];
            int4 w;
            w.x = run; run += v.x;
            w.y = run; run += v.y;
            w.z = run; run += v.z;
            w.w = run; run += v.w;
            o4[i] = w;
            c4[i] = w;
        }
    }
}

// ---------------------------------------------------------------------------
// K3: fill bins (8 edges/thread — round-16 winner config)
// ---------------------------------------------------------------------------
__global__ void fill_kernel(const int* __restrict__ ei,
                            const float* __restrict__ em) {
    int t = blockIdx.x * blockDim.x + threadIdx.x;
    int base = t * 8;
    if (base >= NE) return;
    int b = base / EE;
    int e = base - b * EE;
    const int* eb = ei + (size_t)b * 2 * EE;
    int4 sa = __ldg((const int4*)&eb[e]);
    int4 sb = __ldg((const int4*)&eb[e + 4]);
    int4 ta = __ldg((const int4*)&eb[EE + e]);
    int4 tb = __ldg((const int4*)&eb[EE + e + 4]);
    float4 ma = __ldg((const float4*)&em[(size_t)b * EE + e]);
    float4 mb = __ldg((const float4*)&em[(size_t)b * EE + e + 4]);
    int* cur = g_cursor + b * NN;
    int p0 = atomicAdd(&cur[ta.x], 1);
    int p1 = atomicAdd(&cur[ta.y], 1);
    int p2 = atomicAdd(&cur[ta.z], 1);
    int p3 = atomicAdd(&cur[ta.w], 1);
    int p4 = atomicAdd(&cur[tb.x], 1);
    int p5 = atomicAdd(&cur[tb.y], 1);
    int p6 = atomicAdd(&cur[tb.z], 1);
    int p7 = atomicAdd(&cur[tb.w], 1);
    g_bin[p0] = make_int2(sa.x, __float_as_int(ma.x));
    g_bin[p1] = make_int2(sa.y, __float_as_int(ma.y));
    g_bin[p2] = make_int2(sa.z, __float_as_int(ma.z));
    g_bin[p3] = make_int2(sa.w, __float_as_int(ma.w));
    g_bin[p4] = make_int2(sb.x, __float_as_int(mb.x));
    g_bin[p5] = make_int2(sb.y, __float_as_int(mb.y));
    g_bin[p6] = make_int2(sb.z, __float_as_int(mb.z));
    g_bin[p7] = make_int2(sb.w, __float_as_int(mb.w));
}

// ---------------------------------------------------------------------------
// K4: gather — 64-thread blocks (round-16 WIN) x two independent nodes per
// warp (round-12 shape). Half-warp (16 lanes) per node, lane = uint4 (16B)
// slice of the 256B row; halves share nothing. Chains/SM roughly doubles vs
// round 16 (~450-512) at near-full occupancy.
// ---------------------------------------------------------------------------
#define GATHER_TPB 64

__global__ void __launch_bounds__(GATHER_TPB) gather_kernel() {
    int gw = (blockIdx.x * blockDim.x + threadIdx.x) >> 5;   // warp id
    int lane = threadIdx.x & 31;
    int g = gw * 2 + (lane >> 4);            // node for this half-warp
    int hl = lane & 15;                      // uint4 slice within the row
    if (g >= NB) return;
    int b = g / NN;

    const int deg = g_deg[g];
    const int off = g_off[g];
    const uint4* xr = (const uint4*)g_xh + (size_t)b * NN * 16;  // 16 uint4/row
    const int2* bin = g_bin + off;

    float acc[8] = {0.f, 0.f, 0.f, 0.f, 0.f, 0.f, 0.f, 0.f};
    float cm = 0.f;

#define EDGE_FMA(u, m)                                                        \
    {                                                                         \
        float2 f0 = __half22float2(*(__half2*)&(u).x);                        \
        float2 f1 = __half22float2(*(__half2*)&(u).y);                        \
        float2 f2 = __half22float2(*(__half2*)&(u).z);                        \
        float2 f3 = __half22float2(*(__half2*)&(u).w);                        \
        acc[0] = fmaf(f0.x, (m), acc[0]);                                     \
        acc[1] = fmaf(f0.y, (m), acc[1]);                                     \
        acc[2] = fmaf(f1.x, (m), acc[2]);                                     \
        acc[3] = fmaf(f1.y, (m), acc[3]);                                     \
        acc[4] = fmaf(f2.x, (m), acc[4]);                                     \
        acc[5] = fmaf(f2.y, (m), acc[5]);                                     \
        acc[6] = fmaf(f3.x, (m), acc[6]);                                     \
        acc[7] = fmaf(f3.y, (m), acc[7]);                                     \
        cm += (m);                                                            \
    }

    int j = 0;
    for (; j + 4 <= deg; j += 4) {
        int2 r0 = __ldg(&bin[j]);
        int2 r1 = __ldg(&bin[j + 1]);
        int2 r2 = __ldg(&bin[j + 2]);
        int2 r3 = __ldg(&bin[j + 3]);
        uint4 u0 = __ldg(&xr[(size_t)(u32)r0.x * 16 + hl]);
        uint4 u1 = __ldg(&xr[(size_t)(u32)r1.x * 16 + hl]);
        uint4 u2 = __ldg(&xr[(size_t)(u32)r2.x * 16 + hl]);
        uint4 u3 = __ldg(&xr[(size_t)(u32)r3.x * 16 + hl]);
        EDGE_FMA(u0, __int_as_float(r0.y))
        EDGE_FMA(u1, __int_as_float(r1.y))
        EDGE_FMA(u2, __int_as_float(r2.y))
        EDGE_FMA(u3, __int_as_float(r3.y))
    }
    for (; j < deg; ++j) {
        int2 r = __ldg(&bin[j]);
        uint4 u = __ldg(&xr[(size_t)(u32)r.x * 16 + hl]);
        EDGE_FMA(u, __int_as_float(r.y))
    }
#undef EDGE_FMA

    float inv = 1.f / fmaxf(cm, 1.f);
    __half2 h0 = __floats2half2_rn(acc[0] * inv, acc[1] * inv);
    __half2 h1 = __floats2half2_rn(acc[2] * inv, acc[3] * inv);
    __half2 h2 = __floats2half2_rn(acc[4] * inv, acc[5] * inv);
    __half2 h3 = __floats2half2_rn(acc[6] * inv, acc[7] * inv);
    uint4 o = make_uint4(*(u32*)&h0, *(u32*)&h1, *(u32*)&h2, *(u32*)&h3);
    ((uint4*)g_meanh)[(size_t)g * 16 + hl] = o;
}

// ---------------------------------------------------------------------------
// K5: fused HMMA GEMM + relu + LN + mask (unchanged from round 5).
// ---------------------------------------------------------------------------
#define FUSED_THREADS 256
#define IN_PITCH 264
#define W_PITCH_H 136
#define SMEM_WH_BYTES (256 * W_PITCH_H * 2)
#define SMEM_IN_BYTES (128 * IN_PITCH * 2)
#define SMEM_CONST_BYTES (3 * 128 * 4)
#define FUSED_SMEM_BYTES (SMEM_WH_BYTES + SMEM_IN_BYTES + SMEM_CONST_BYTES)
#define NTILES ((NB + 127) / 128)             // 313

__device__ __forceinline__ u32 smem_u32(const void* p) {
    u32 a;
    asm("{ .reg .u64 t; cvta.to.shared.u64 t, %1; cvt.u32.u64 %0, t; }"
        : "=r"(a) : "l"(p));
    return a;
}
__device__ __forceinline__ void ldsm_x4(u32& r0, u32& r1, u32& r2, u32& r3, u32 a) {
    asm volatile("ldmatrix.sync.aligned.m8n8.x4.shared.b16 {%0,%1,%2,%3}, [%4];"
                 : "=r"(r0), "=r"(r1), "=r"(r2), "=r"(r3) : "r"(a));
}
__device__ __forceinline__ void ldsm_x4t(u32& r0, u32& r1, u32& r2, u32& r3, u32 a) {
    asm volatile("ldmatrix.sync.aligned.m8n8.x4.trans.shared.b16 {%0,%1,%2,%3}, [%4];"
                 : "=r"(r0), "=r"(r1), "=r"(r2), "=r"(r3) : "r"(a));
}
__device__ __forceinline__ void mma16816(float* c, u32 a0, u32 a1, u32 a2, u32 a3,
                                         u32 b0, u32 b1) {
    asm volatile(
        "mma.sync.aligned.m16n8k16.row.col.f32.f16.f16.f32 "
        "{%0,%1,%2,%3}, {%4,%5,%6,%7}, {%8,%9}, {%0,%1,%2,%3};"
        : "+f"(c[0]), "+f"(c[1]), "+f"(c[2]), "+f"(c[3])
        : "r"(a0), "r"(a1), "r"(a2), "r"(a3), "r"(b0), "r"(b1));
}

__global__ void __launch_bounds__(FUSED_THREADS, 1)
fused_kernel(const float* __restrict__ Wself,
             const float* __restrict__ bself,
             const float* __restrict__ Wnb,
             const float* __restrict__ bnb,
             const float* __restrict__ gamma,
             const float* __restrict__ beta,
             const float* __restrict__ nmask,
             float* __restrict__ out) {
    extern __shared__ char sm[];
    __half* Wh = (__half*)sm;
    __half* inSh = (__half*)(sm + SMEM_WH_BYTES);
    float* bias_sm = (float*)(sm + SMEM_WH_BYTES + SMEM_IN_BYTES);
    float* gm_sm = bias_sm + 128;
    float* bt_sm = gm_sm + 128;

    const int tid = threadIdx.x;
    const int lane = tid & 31;
    const int wid = tid >> 5;

    for (int i = tid; i < 256 * 128; i += FUSED_THREADS) {
        int k = i >> 7;
        int n = i & 127;
        float w = (k < 128) ? __ldg(&Wself[k * 128 + n])
                            : __ldg(&Wnb[(k - 128) * 128 + n]);
        Wh[k * W_PITCH_H + n] = __float2half_rn(w);
    }
    if (tid < 128) {
        bias_sm[tid] = __ldg(&bself[tid]) + __ldg(&bnb[tid]);
        gm_sm[tid] = __ldg(&gamma[tid]);
        bt_sm[tid] = __ldg(&beta[tid]);
    }
    __syncthreads();

    const u32 in_u = smem_u32(inSh);
    const u32 wh_u = smem_u32(Wh);
    const u32 a_row_off = (u32)(wid * 16 + (lane & 15)) * (IN_PITCH * 2)
                        + (u32)((lane >> 4) * 8) * 2;
    const u32 b_row_lane = (u32)(lane & 15) * (W_PITCH_H * 2);
    const u32 b_col_lane = (u32)((lane >> 4) * 8) * 2;

    for (int tile = blockIdx.x; tile < NTILES; tile += gridDim.x) {
        const int node0 = tile * 128;

        for (int i = tid; i < 128 * 64; i += FUSED_THREADS) {
            int nl = i >> 6;
            int c = i & 63;
            int gn = node0 + nl;
            uint2 v = make_uint2(0u, 0u);
            if (gn < NB)
                v = (c < 32) ? __ldg(&g_xh[(size_t)gn * 32 + c])
                             : __ldg(&g_meanh[(size_t)gn * 32 + (c - 32)]);
            *(uint2*)((char*)inSh + (size_t)nl * (IN_PITCH * 2) + (size_t)c * 8) = v;
        }
        __syncthreads();

        float acc[16][4];
#pragma unroll
        for (int j = 0; j < 16; ++j) {
            float2 bv = *(float2*)&bias_sm[j * 8 + (lane & 3) * 2];
            acc[j][0] = bv.x; acc[j][1] = bv.y;
            acc[j][2] = bv.x; acc[j][3] = bv.y;
        }

#pragma unroll 1
        for (int ks = 0; ks < 16; ++ks) {
            u32 a0, a1, a2, a3;
            ldsm_x4(a0, a1, a2, a3, in_u + a_row_off + (u32)ks * 32);
            u32 brow = wh_u + (u32)ks * 16 * (W_PITCH_H * 2) + b_row_lane + b_col_lane;
#pragma unroll
            for (int jt = 0; jt < 8; ++jt) {
                u32 b0, b1, b2, b3;
                ldsm_x4t(b0, b1, b2, b3, brow + (u32)jt * 32);
                mma16816(acc[2 * jt], a0, a1, a2, a3, b0, b1);
                mma16816(acc[2 * jt + 1], a0, a1, a2, a3, b2, b3);
            }
        }

#pragma unroll
        for (int j = 0; j < 16; ++j) {
            acc[j][0] = fmaxf(acc[j][0], 0.f);
            acc[j][1] = fmaxf(acc[j][1], 0.f);
            acc[j][2] = fmaxf(acc[j][2], 0.f);
            acc[j][3] = fmaxf(acc[j][3], 0.f);
        }
        float s0 = 0.f, s1 = 0.f;
#pragma unroll
        for (int j = 0; j < 16; ++j) {
            s0 += acc[j][0] + acc[j][1];
            s1 += acc[j][2] + acc[j][3];
        }
        s0 += __shfl_xor_sync(0xFFFFFFFFu, s0, 1);
        s0 += __shfl_xor_sync(0xFFFFFFFFu, s0, 2);
        s1 += __shfl_xor_sync(0xFFFFFFFFu, s1, 1);
        s1 += __shfl_xor_sync(0xFFFFFFFFu, s1, 2);
        float mu0 = s0 * (1.f / 128.f);
        float mu1 = s1 * (1.f / 128.f);

        float v0 = 0.f, v1 = 0.f;
#pragma unroll
        for (int j = 0; j < 16; ++j) {
            float d0 = acc[j][0] - mu0, d1 = acc[j][1] - mu0;
            float d2 = acc[j][2] - mu1, d3 = acc[j][3] - mu1;
            v0 += d0 * d0 + d1 * d1;
            v1 += d2 * d2 + d3 * d3;
        }
        v0 += __shfl_xor_sync(0xFFFFFFFFu, v0, 1);
        v0 += __shfl_xor_sync(0xFFFFFFFFu, v0, 2);
        v1 += __shfl_xor_sync(0xFFFFFFFFu, v1, 1);
        v1 += __shfl_xor_sync(0xFFFFFFFFu, v1, 2);
        float rstd0 = rsqrtf(v0 * (1.f / 128.f) + 1e-5f);
        float rstd1 = rsqrtf(v1 * (1.f / 128.f) + 1e-5f);

        int r0 = node0 + wid * 16 + (lane >> 2);
        int r1 = r0 + 8;
        float mk0 = (r0 < NB) ? __ldg(&nmask[r0]) : 0.f;
        float mk1 = (r1 < NB) ? __ldg(&nmask[r1]) : 0.f;
        float a0s = rstd0 * mk0, a1s = rstd1 * mk1;

#pragma unroll
        for (int j = 0; j < 16; ++j) {
            int col = j * 8 + (lane & 3) * 2;
            float2 g2 = *(float2*)&gm_sm[col];
            float2 b2 = *(float2*)&bt_sm[col];
            if (r0 < NB) {
                float2 o;
                o.x = ((acc[j][0] - mu0) * g2.x * a0s) + b2.x * mk0;
                o.y = ((acc[j][1] - mu0) * g2.y * a0s) + b2.y * mk0;
                *(float2*)&out[(size_t)r0 * 128 + col] = o;
            }
            if (r1 < NB) {
                float2 o;
                o.x = ((acc[j][2] - mu1) * g2.x * a1s) + b2.x * mk1;
                o.y = ((acc[j][3] - mu1) * g2.y * a1s) + b2.y * mk1;
                *(float2*)&out[(size_t)r1 * 128 + col] = o;
            }
        }
        __syncthreads();
    }
}

// ---------------------------------------------------------------------------
extern "C" void kernel_launch(void* const* d_in, const int* in_sizes, int n_in,
                              void* d_out, int out_size) {
    const float* x     = (const float*)d_in[0];
    const int*   ei    = (const int*)d_in[1];
    const float* nmask = (const float*)d_in[2];
    const float* emask = (const float*)d_in[3];
    const float* Wself = (const float*)d_in[4];
    const float* bself = (const float*)d_in[5];
    const float* Wnb   = (const float*)d_in[6];
    const float* bnb   = (const float*)d_in[7];
    const float* gamma = (const float*)d_in[8];
    const float* beta  = (const float*)d_in[9];
    float* out = (float*)d_out;

    (void)in_sizes; (void)n_in; (void)out_size;

    prep_kernel<<<(NB * DD / 4 + 255) / 256, 256>>>(x);
    hist_kernel<<<(NE / 4 + 255) / 256, 256>>>(ei);
    scan_kernel<<<1, 1024>>>();
    fill_kernel<<<(NE / 8 + 255) / 256, 256>>>(ei, emask);
    // 2 nodes/warp -> NB/2 warps total
    gather_kernel<<<((NB / 2) * 32 + GATHER_TPB - 1) / GATHER_TPB, GATHER_TPB>>>();

    cudaFuncSetAttribute(fused_kernel, cudaFuncAttributeMaxDynamicSharedMemorySize,
                         FUSED_SMEM_BYTES);
    int nsm = 148;
    cudaDeviceGetAttribute(&nsm, cudaDevAttrMultiProcessorCount, 0);
    fused_kernel<<<nsm, FUSED_THREADS, FUSED_SMEM_BYTES>>>(
        Wself, bself, Wnb, bnb, gamma, beta, nmask, out);
}